// round 12
// baseline (speedup 1.0000x reference)
#include <cuda_runtime.h>
#include <cuda_bf16.h>

// CASSI forward A^T(A(x)); coded aperture is band-broadcast (phi[l]==phi2d):
//   y2[b,m,j]    = sum_{l : 0<=j-2l<N} x[b,l,m,j-2l]*phi2d[m,j-2l]
//   out[b,l,m,n] = phi2d[m,n] * y2[b,m,n+2l]
// L=28, M=N=256, STRIDE=2, n_out=310.
//
// R12 = R9/R11 + multi-row pipelined CTA: each CTA handles ROWS consecutive
// m-rows; phase 1 of row r+1 is fused with phase 3 of row r (LDG next row
// interleaved with STG current row). Single prod buffer — hazard-free:
//   sync1: prod(r) ready for phase2 ; sync2: y2 ready AND prod consumed,
//   so fused phase1(r+1) may overwrite prod while phase3(r) reads y2.

#define LBANDS 28
#define NCOLS  256
#define NC4    (NCOLS / 4)                        // 64 float4 per row
#define NOUT   (NCOLS + 2 * (LBANDS - 1))         // 310
#define THREADS 256
#define MNFIX  (NCOLS * NCOLS)
#define BAND4  (MNFIX / 4)                        // float4 stride between bands
#define ROWS   4                                  // rows per CTA

__global__ __launch_bounds__(THREADS, 6)
void cassi_kernel(const float4* __restrict__ x4,
                  const float4* __restrict__ phi4,
                  float4* __restrict__ out4,
                  int LMN4 /* L*M*N/4 */)
{
    __shared__ float prod[LBANDS * NCOLS];   // 28 KB, single buffer
    __shared__ float y2 [320];
    __shared__ float y2s[320];               // y2s[j] == y2[j+2]
    float4* prod4 = reinterpret_cast<float4*>(prod);

    const int m0  = blockIdx.x * ROWS;
    const int b   = blockIdx.y;
    const int tid = threadIdx.x;

    const int lsub = tid >> 6;        // 0..3, uniform per warp-pair
    const int c    = tid & 63;        // float4 column 0..63

    // phase-3 y2 addressing (row-independent)
    const float* ybase = (lsub & 1) ? y2s : y2;
    const int yo4base  = ((c << 2) + 2 * lsub - ((lsub & 1) << 1)) >> 2;

    // ---- prologue: phase 1 of row m0 ----
    float4 pv = phi4[m0 * NC4 + c];          // phi2d row, band-independent
    {
        int xo = b * LMN4 + m0 * NC4 + lsub * BAND4 + c;
        int so = lsub * NC4 + c;
#pragma unroll
        for (int k = 0; k < LBANDS / 4; ++k) {
            const float4 xv = x4[xo];
            float4 pr;
            pr.x = xv.x * pv.x; pr.y = xv.y * pv.y;
            pr.z = xv.z * pv.z; pr.w = xv.w * pv.w;
            prod4[so] = pr;
            xo += 4 * BAND4; so += 4 * NC4;
        }
    }

#pragma unroll 1
    for (int r = 0; r < ROWS; ++r) {
        const int m = m0 + r;
        __syncthreads();                     // prod(r) ready

        // ---- phase 2: y2[j],y2[j+1] (j even) via aligned LDS.64 ----
        {
            const int j = tid << 1;          // 0,2,...,510
            if (j < NOUT) {
                float sx = 0.0f, sy = 0.0f;
                const float* pb = prod + j;
                if (j >= 2 * (LBANDS - 1) && j < NCOLS) {
#pragma unroll
                    for (int l = 0; l < LBANDS; ++l) {
                        const float2 p =
                            *reinterpret_cast<const float2*>(pb + l * (NCOLS - 2));
                        sx += p.x; sy += p.y;
                    }
                } else {
                    const int lmin = (j >= NCOLS) ? ((j - (NCOLS - 2)) >> 1) : 0;
                    const int jh   = j >> 1;
                    const int lmax = jh < (LBANDS - 1) ? jh : (LBANDS - 1);
                    for (int l = lmin; l <= lmax; ++l) {
                        const float2 p =
                            *reinterpret_cast<const float2*>(pb + l * (NCOLS - 2));
                        sx += p.x; sy += p.y;
                    }
                }
                *reinterpret_cast<float2*>(y2 + j) = make_float2(sx, sy);
                if (j >= 2)
                    *reinterpret_cast<float2*>(y2s + j - 2) = make_float2(sx, sy);
            }
        }
        __syncthreads();                     // y2 ready; prod consumed

        // ---- fused: phase 3(row r) + phase 1(row r+1) ----
        const bool more = (r + 1 < ROWS);
        float4 pvn = pv;
        if (more) pvn = phi4[(m + 1) * NC4 + c];

        int oo  = b * LMN4 + m * NC4 + lsub * BAND4 + c;
        int xo  = oo + NC4;                  // row m+1, same band/column
        int so  = lsub * NC4 + c;
        int yo4 = yo4base;
#pragma unroll
        for (int k = 0; k < LBANDS / 4; ++k) {
            float4 xv;
            if (more) xv = x4[xo];           // next-row load, issued early
            const float4 yv = reinterpret_cast<const float4*>(ybase)[yo4];
            float4 ov;
            ov.x = pv.x * yv.x; ov.y = pv.y * yv.y;
            ov.z = pv.z * yv.z; ov.w = pv.w * yv.w;
            out4[oo] = ov;                   // current-row store
            if (more) {
                float4 pr;
                pr.x = xv.x * pvn.x; pr.y = xv.y * pvn.y;
                pr.z = xv.z * pvn.z; pr.w = xv.w * pvn.w;
                prod4[so] = pr;              // stage next row
            }
            oo += 4 * BAND4; xo += 4 * BAND4; so += 4 * NC4;
            yo4 += 2;
        }
        pv = pvn;
    }
}

extern "C" void kernel_launch(void* const* d_in, const int* in_sizes, int n_in,
                              void* d_out, int out_size)
{
    const float4* x4   = (const float4*)d_in[0];   // [B, L, M, N]
    const float4* phi4 = (const float4*)d_in[1];   // [L, M, N] (band-broadcast)
    float4* out4 = (float4*)d_out;

    const int LMN  = in_sizes[1];        // L*M*N
    const int B    = in_sizes[0] / LMN;  // batch
    const int LMN4 = LMN / 4;

    dim3 grid(NCOLS / ROWS, B);          // 64 x 32 = 2048 CTAs
    cassi_kernel<<<grid, THREADS>>>(x4, phi4, out4, LMN4);
}